// round 16
// baseline (speedup 1.0000x reference)
#include <cuda_runtime.h>
#include <cuda_bf16.h>
#include <math.h>
#include <cstdint>

// Stickbreaking attention, B=1, H=16, S=2048, Dh=64, fp32.
//
// fp32-faithful structure:
//  (1) Mask(-1e9)-before-cumsum => every query row except i=S-1 is exactly 0
//      (expf underflow of the -1e9 carry).
//  (2) Row S-1: suffix sums S_t of log_sigmoid(-l) are monotone non-increasing.
//      Once carry < -30, total remaining weight mass <= S*e^-30 ~ 2e-10 of the
//      O(1) accumulator -- far below the 1e-3 gate and fp32 resolution.
//      E[carry after 64 keys] ~ -52 +- 6.2 => one 64-key chunk suffices
//      ~99.98% of the time; the fallback loop keeps any-input correctness.
//
// Grid = 148, one wave. Blocks 0..15: one head each, register-direct
// (6 independent LDG.128/thread), straight-line hot chunk, MUFU
// transcendentals (__expf/__logf: ~1e-7 rel err/term, 1000x under the gate).
// Blocks 16..147: zero the output (skipping last rows, owned by compute).

#define SB_H  16
#define SB_S  2048
#define SB_D  64
#define SB_SCALE 0.125f
#define SB_NBLK  148
#define SB_CHUNK 64
#define SB_CUTOFF -30.0f

// p = log_sigmoid(-l) = -softplus(l), fast path
__device__ __forceinline__ float sb_logsig_neg(float l) {
    return -(fmaxf(l, 0.f) + __logf(1.f + __expf(-fabsf(l))));
}

__global__ __launch_bounds__(512, 1)
void sb_fused_kernel(const float* __restrict__ q,
                     const float* __restrict__ k,
                     const float* __restrict__ v,
                     float* __restrict__ out) {
    const int bid = blockIdx.x;
    const int tid = threadIdx.x;

    if (bid >= SB_H) {
        // ---------------- zero path ----------------
        float4* o4 = reinterpret_cast<float4*>(out);
        const int total4 = SB_H * SB_S * SB_D / 4;     // 524288
        const int per_head4 = SB_S * SB_D / 4;         // 32768
        const int stride = (SB_NBLK - SB_H) * 512;
        const float4 z4 = make_float4(0.f, 0.f, 0.f, 0.f);
        for (int i = (bid - SB_H) * 512 + tid; i < total4; i += stride) {
            if ((i & (per_head4 - 1)) < per_head4 - (SB_D / 4))
                o4[i] = z4;
        }
        return;
    }

    // ---------------- compute path: head h = bid ----------------
    __shared__ float  ws16[16];        // warp scan totals
    __shared__ float  wsm[SB_CHUNK];   // weights (key-indexed)
    __shared__ float4 red4[512];       // reduction scratch

    const int lane = tid & 31;
    const int wid  = tid >> 5;         // 16 warps
    const int oc   = tid & 7;          // octant of dot (8 threads/key)
    const int key  = tid >> 3;         // 0..63 (scan order within chunk)
    const int kg   = tid >> 4;         // matvec key-group (2 keys)
    const int d4   = tid & 15;         // float4 dim slot

    const size_t head_base = (size_t)bid * SB_S * SB_D;
    const float4* q4 = reinterpret_cast<const float4*>(q + head_base + (size_t)(SB_S - 1) * SB_D);
    const float4* k4 = reinterpret_cast<const float4*>(k + head_base);
    const float4* v4 = reinterpret_cast<const float4*>(v + head_base);

    const int r_dot = (SB_CHUNK - 1) - key;            // chunk row of this key
    const int r_mv0 = (SB_CHUNK - 1) - (kg * 2 + 0);   // matvec rows
    const int r_mv1 = (SB_CHUNK - 1) - (kg * 2 + 1);

    // ---- front-load ALL hot-chunk traffic: 2 q + 2 K + 2 V LDG.128 ----
    const int jb0 = SB_S - SB_CHUNK;
    const float4 qv0 = q4[oc * 2 + 0];
    const float4 qv1 = q4[oc * 2 + 1];
    const float4 kv0 = k4[(size_t)(jb0 + r_dot) * 16 + oc * 2 + 0];
    const float4 kv1 = k4[(size_t)(jb0 + r_dot) * 16 + oc * 2 + 1];
    const float4 vv0 = v4[(size_t)(jb0 + r_mv0) * 16 + d4];
    const float4 vv1 = v4[(size_t)(jb0 + r_mv1) * 16 + d4];

    float4 acc = make_float4(0.f, 0.f, 0.f, 0.f);
    float carry = 0.f;

    // ================= hot chunk (keys t=0..63), straight-line =================
    {
        float dot = kv0.x * qv0.x + kv0.y * qv0.y + kv0.z * qv0.z + kv0.w * qv0.w
                  + kv1.x * qv1.x + kv1.y * qv1.y + kv1.z * qv1.z + kv1.w * qv1.w;
        dot += __shfl_xor_sync(0xFFFFFFFFu, dot, 1);
        dot += __shfl_xor_sync(0xFFFFFFFFu, dot, 2);
        dot += __shfl_xor_sync(0xFFFFFFFFu, dot, 4);
        const float l = dot * SB_SCALE;
        const float p = sb_logsig_neg(l);

        float ws = (oc == 0) ? p : 0.f;
        #pragma unroll
        for (int off = 1; off < 32; off <<= 1) {
            float n = __shfl_up_sync(0xFFFFFFFFu, ws, off);
            if (lane >= off) ws += n;
        }
        if (lane == 31) ws16[wid] = ws;
        __syncthreads();                               // sync A

        float warp_excl = 0.f, btot = 0.f;
        #pragma unroll
        for (int w = 0; w < 16; w++) {
            const float s = ws16[w];
            btot += s;
            if (w < wid) warp_excl += s;
        }
        if (oc == 0) {
            const float S_t = warp_excl + ws;          // carry==0 for hot chunk
            const float z = 1.f / (1.f + __expf(-l));
            wsm[key] = z * __expf(S_t);
        }
        carry = btot;
        __syncthreads();                               // sync B

        const float w0 = wsm[kg * 2 + 0];
        const float w1 = wsm[kg * 2 + 1];
        acc.x += w0 * vv0.x + w1 * vv1.x;
        acc.y += w0 * vv0.y + w1 * vv1.y;
        acc.z += w0 * vv0.z + w1 * vv1.z;
        acc.w += w0 * vv0.w + w1 * vv1.w;
    }

    // ============ rare fallback chunks (P ~ 2e-4 per head) ============
    for (int c = 1; (c < SB_S / SB_CHUNK) && (carry >= SB_CUTOFF); c++) {
        __syncthreads();                               // protect ws16/wsm
        const int jb = SB_S - (c + 1) * SB_CHUNK;

        const float4 fk0 = k4[(size_t)(jb + r_dot) * 16 + oc * 2 + 0];
        const float4 fk1 = k4[(size_t)(jb + r_dot) * 16 + oc * 2 + 1];
        const float4 fv0 = v4[(size_t)(jb + r_mv0) * 16 + d4];
        const float4 fv1 = v4[(size_t)(jb + r_mv1) * 16 + d4];

        float dot = fk0.x * qv0.x + fk0.y * qv0.y + fk0.z * qv0.z + fk0.w * qv0.w
                  + fk1.x * qv1.x + fk1.y * qv1.y + fk1.z * qv1.z + fk1.w * qv1.w;
        dot += __shfl_xor_sync(0xFFFFFFFFu, dot, 1);
        dot += __shfl_xor_sync(0xFFFFFFFFu, dot, 2);
        dot += __shfl_xor_sync(0xFFFFFFFFu, dot, 4);
        const float l = dot * SB_SCALE;
        const float p = sb_logsig_neg(l);

        float ws = (oc == 0) ? p : 0.f;
        #pragma unroll
        for (int off = 1; off < 32; off <<= 1) {
            float n = __shfl_up_sync(0xFFFFFFFFu, ws, off);
            if (lane >= off) ws += n;
        }
        if (lane == 31) ws16[wid] = ws;
        __syncthreads();

        float warp_excl = 0.f, btot = 0.f;
        #pragma unroll
        for (int w = 0; w < 16; w++) {
            const float s = ws16[w];
            btot += s;
            if (w < wid) warp_excl += s;
        }
        if (oc == 0) {
            const float S_t = carry + warp_excl + ws;
            const float z = 1.f / (1.f + __expf(-l));
            wsm[key] = z * __expf(S_t);
        }
        carry += btot;
        __syncthreads();

        const float w0 = wsm[kg * 2 + 0];
        const float w1 = wsm[kg * 2 + 1];
        acc.x += w0 * fv0.x + w1 * fv1.x;
        acc.y += w0 * fv0.y + w1 * fv1.y;
        acc.z += w0 * fv0.z + w1 * fv1.z;
        acc.w += w0 * fv0.w + w1 * fv1.w;
    }

    // ---- flat reduction: 512 partials -> 16 float4 ----
    red4[tid] = acc;
    __syncthreads();
    if (tid < 16) {
        float4 s = make_float4(0.f, 0.f, 0.f, 0.f);
        #pragma unroll
        for (int g = 0; g < 32; g++) {
            const float4 b = red4[g * 16 + tid];
            s.x += b.x; s.y += b.y; s.z += b.z; s.w += b.w;
        }
        float4* out4 = reinterpret_cast<float4*>(out + head_base + (size_t)(SB_S - 1) * SB_D);
        out4[tid] = s;
    }
}

extern "C" void kernel_launch(void* const* d_in, const int* in_sizes, int n_in,
                              void* d_out, int out_size) {
    const float* q = (const float*)d_in[0];
    const float* k = (const float*)d_in[1];
    const float* v = (const float*)d_in[2];
    float* out = (float*)d_out;
    sb_fused_kernel<<<SB_NBLK, 512>>>(q, k, v, out);
}

// round 17
// speedup vs baseline: 1.0238x; 1.0238x over previous
#include <cuda_runtime.h>
#include <cuda_bf16.h>
#include <math.h>
#include <cstdint>

// Stickbreaking attention, B=1, H=16, S=2048, Dh=64, fp32.
//
// fp32-faithful structure:
//  (1) Mask(-1e9)-before-cumsum => every query row except i=S-1 is exactly 0
//      (expf underflow of the -1e9 carry).
//  (2) Row S-1: suffix sums S_t of log_sigmoid(-l) are monotone non-increasing.
//      Once carry < -30, total remaining weight mass <= S*e^-30 ~ 2e-10 of the
//      O(1) accumulator -- far below the 1e-3 gate and fp32 resolution.
//      E[carry after 64 keys] ~ -52 +- 6.2 => one 64-key chunk suffices
//      ~99.98% of the time; the fallback loop keeps any-input correctness.
//
// Grid = 148, one wave. Blocks 0..15: one head each, register-direct
// (6 independent LDG.128/thread). Key trick: seeding the warp scan with p at
// ALL 8 lanes of a key group lets a 2-step (stride 8,16) scan leave every
// lane holding the inclusive sum through its own key -> every thread computes
// its own weight locally; matvec weights arrive via 2 intra-warp shfls.
// No wsm array, one barrier per chunk. MUFU transcendentals (~1e-7/term).
// Blocks 16..147: zero the output (skipping last rows, owned by compute).

#define SB_H  16
#define SB_S  2048
#define SB_D  64
#define SB_SCALE 0.125f
#define SB_NBLK  148
#define SB_CHUNK 64
#define SB_CUTOFF -30.0f

// p = log_sigmoid(-l) = -softplus(l), fast path
__device__ __forceinline__ float sb_logsig_neg(float l) {
    return -(fmaxf(l, 0.f) + __logf(1.f + __expf(-fabsf(l))));
}

__global__ __launch_bounds__(512, 1)
void sb_fused_kernel(const float* __restrict__ q,
                     const float* __restrict__ k,
                     const float* __restrict__ v,
                     float* __restrict__ out) {
    const int bid = blockIdx.x;
    const int tid = threadIdx.x;

    if (bid >= SB_H) {
        // ---------------- zero path ----------------
        float4* o4 = reinterpret_cast<float4*>(out);
        const int total4 = SB_H * SB_S * SB_D / 4;     // 524288
        const int per_head4 = SB_S * SB_D / 4;         // 32768
        const int stride = (SB_NBLK - SB_H) * 512;
        const float4 z4 = make_float4(0.f, 0.f, 0.f, 0.f);
        for (int i = (bid - SB_H) * 512 + tid; i < total4; i += stride) {
            if ((i & (per_head4 - 1)) < per_head4 - (SB_D / 4))
                o4[i] = z4;
        }
        return;
    }

    // ---------------- compute path: head h = bid ----------------
    __shared__ float  ws16[16];        // warp scan totals (float4-aligned)
    __shared__ float4 red4[512];       // reduction scratch

    const int lane = tid & 31;
    const int wid  = tid >> 5;         // 16 warps
    const int oc   = tid & 7;          // octant of dot (8 threads/key)
    const int key  = tid >> 3;         // 0..63 (scan order within chunk)
    const int kg   = tid >> 4;         // matvec key-group (2 keys)
    const int d4   = tid & 15;         // float4 dim slot

    const size_t head_base = (size_t)bid * SB_S * SB_D;
    const float4* q4 = reinterpret_cast<const float4*>(q + head_base + (size_t)(SB_S - 1) * SB_D);
    const float4* k4 = reinterpret_cast<const float4*>(k + head_base);
    const float4* v4 = reinterpret_cast<const float4*>(v + head_base);

    const int r_dot = (SB_CHUNK - 1) - key;            // chunk row of this key
    const int r_mv0 = (SB_CHUNK - 1) - (kg * 2 + 0);   // matvec rows
    const int r_mv1 = (SB_CHUNK - 1) - (kg * 2 + 1);

    // matvec weight shfl sources (intra-warp; warp w holds keys 4w..4w+3)
    const int wsrc0 = lane & 16;       // key 2kg   -> lane 0 or 16
    const int wsrc1 = wsrc0 + 8;       // key 2kg+1 -> lane 8 or 24

    // ---- front-load ALL hot-chunk traffic: 2 q + 2 K + 2 V LDG.128 ----
    const int jb0 = SB_S - SB_CHUNK;
    const float4 qv0 = q4[oc * 2 + 0];
    const float4 qv1 = q4[oc * 2 + 1];
    const float4 kv0 = k4[(size_t)(jb0 + r_dot) * 16 + oc * 2 + 0];
    const float4 kv1 = k4[(size_t)(jb0 + r_dot) * 16 + oc * 2 + 1];
    const float4 vv0 = v4[(size_t)(jb0 + r_mv0) * 16 + d4];
    const float4 vv1 = v4[(size_t)(jb0 + r_mv1) * 16 + d4];

    float4 acc = make_float4(0.f, 0.f, 0.f, 0.f);
    float carry = 0.f;

    // ================= hot chunk (keys t=0..63), straight-line =================
    {
        float dot = kv0.x * qv0.x + kv0.y * qv0.y + kv0.z * qv0.z + kv0.w * qv0.w
                  + kv1.x * qv1.x + kv1.y * qv1.y + kv1.z * qv1.z + kv1.w * qv1.w;
        dot += __shfl_xor_sync(0xFFFFFFFFu, dot, 1);
        dot += __shfl_xor_sync(0xFFFFFFFFu, dot, 2);
        dot += __shfl_xor_sync(0xFFFFFFFFu, dot, 4);   // all 8 lanes share l
        const float l = dot * SB_SCALE;
        const float p = sb_logsig_neg(l);

        // ---- 2-step key scan: seed p at ALL lanes; strides 8,16 ----
        float ws = p;
        {
            float n = __shfl_up_sync(0xFFFFFFFFu, ws, 8);
            if (lane >= 8)  ws += n;
            n = __shfl_up_sync(0xFFFFFFFFu, ws, 16);
            if (lane >= 16) ws += n;
        }
        // every lane: ws = inclusive p-sum through its own key (within warp)
        if (lane == 31) ws16[wid] = ws;                // warp total (4 keys)
        __syncthreads();                               // sync A

        float warp_excl = 0.f, btot = 0.f;
        const float4* w4 = reinterpret_cast<const float4*>(ws16);
        #pragma unroll
        for (int g = 0; g < 4; g++) {
            const float4 t = w4[g];
            btot += t.x + t.y + t.z + t.w;
            const int b = g * 4;
            warp_excl += (b + 0 < wid ? t.x : 0.f) + (b + 1 < wid ? t.y : 0.f)
                       + (b + 2 < wid ? t.z : 0.f) + (b + 3 < wid ? t.w : 0.f);
        }

        // ---- every lane computes its own key's weight ----
        const float S_t = warp_excl + ws;              // carry==0 in hot chunk
        const float z = 1.f / (1.f + __expf(-l));
        const float w_own = z * __expf(S_t);
        carry = btot;

        // ---- matvec: weights via intra-warp shfl ----
        const float w0 = __shfl_sync(0xFFFFFFFFu, w_own, wsrc0);
        const float w1 = __shfl_sync(0xFFFFFFFFu, w_own, wsrc1);
        acc.x += w0 * vv0.x + w1 * vv1.x;
        acc.y += w0 * vv0.y + w1 * vv1.y;
        acc.z += w0 * vv0.z + w1 * vv1.z;
        acc.w += w0 * vv0.w + w1 * vv1.w;
    }

    // ============ rare fallback chunks (P ~ 2e-4 per head) ============
    for (int c = 1; (c < SB_S / SB_CHUNK) && (carry >= SB_CUTOFF); c++) {
        __syncthreads();                               // protect ws16 reuse
        const int jb = SB_S - (c + 1) * SB_CHUNK;

        const float4 fk0 = k4[(size_t)(jb + r_dot) * 16 + oc * 2 + 0];
        const float4 fk1 = k4[(size_t)(jb + r_dot) * 16 + oc * 2 + 1];
        const float4 fv0 = v4[(size_t)(jb + r_mv0) * 16 + d4];
        const float4 fv1 = v4[(size_t)(jb + r_mv1) * 16 + d4];

        float dot = fk0.x * qv0.x + fk0.y * qv0.y + fk0.z * qv0.z + fk0.w * qv0.w
                  + fk1.x * qv1.x + fk1.y * qv1.y + fk1.z * qv1.z + fk1.w * qv1.w;
        dot += __shfl_xor_sync(0xFFFFFFFFu, dot, 1);
        dot += __shfl_xor_sync(0xFFFFFFFFu, dot, 2);
        dot += __shfl_xor_sync(0xFFFFFFFFu, dot, 4);
        const float l = dot * SB_SCALE;
        const float p = sb_logsig_neg(l);

        float ws = p;
        {
            float n = __shfl_up_sync(0xFFFFFFFFu, ws, 8);
            if (lane >= 8)  ws += n;
            n = __shfl_up_sync(0xFFFFFFFFu, ws, 16);
            if (lane >= 16) ws += n;
        }
        if (lane == 31) ws16[wid] = ws;
        __syncthreads();

        float warp_excl = 0.f, btot = 0.f;
        const float4* w4 = reinterpret_cast<const float4*>(ws16);
        #pragma unroll
        for (int g = 0; g < 4; g++) {
            const float4 t = w4[g];
            btot += t.x + t.y + t.z + t.w;
            const int b = g * 4;
            warp_excl += (b + 0 < wid ? t.x : 0.f) + (b + 1 < wid ? t.y : 0.f)
                       + (b + 2 < wid ? t.z : 0.f) + (b + 3 < wid ? t.w : 0.f);
        }

        const float S_t = carry + warp_excl + ws;
        const float z = 1.f / (1.f + __expf(-l));
        const float w_own = z * __expf(S_t);
        carry += btot;

        const float w0 = __shfl_sync(0xFFFFFFFFu, w_own, wsrc0);
        const float w1 = __shfl_sync(0xFFFFFFFFu, w_own, wsrc1);
        acc.x += w0 * fv0.x + w1 * fv1.x;
        acc.y += w0 * fv0.y + w1 * fv1.y;
        acc.z += w0 * fv0.z + w1 * fv1.z;
        acc.w += w0 * fv0.w + w1 * fv1.w;
    }

    // ---- flat reduction: 512 partials -> 16 float4 ----
    red4[tid] = acc;
    __syncthreads();
    if (tid < 16) {
        float4 s = make_float4(0.f, 0.f, 0.f, 0.f);
        #pragma unroll
        for (int g = 0; g < 32; g++) {
            const float4 b = red4[g * 16 + tid];
            s.x += b.x; s.y += b.y; s.z += b.z; s.w += b.w;
        }
        float4* out4 = reinterpret_cast<float4*>(out + head_base + (size_t)(SB_S - 1) * SB_D);
        out4[tid] = s;
    }
}

extern "C" void kernel_launch(void* const* d_in, const int* in_sizes, int n_in,
                              void* d_out, int out_size) {
    const float* q = (const float*)d_in[0];
    const float* k = (const float*)d_in[1];
    const float* v = (const float*)d_in[2];
    float* out = (float*)d_out;
    sb_fused_kernel<<<SB_NBLK, 512>>>(q, k, v, out);
}